// round 12
// baseline (speedup 1.0000x reference)
#include <cuda_runtime.h>
#include <cuda_bf16.h>
#include <cstdint>

// Problem constants (match reference)
#define NXg 2048
#define NYg 2048
#define INV_H  2048.0f   // 1/hx = 1/hy
#define INV_2H 1024.0f   // 1/(2hx)

#define ROWS_PER_THREAD 4
#define TPB 128
#define OPR (NYg / 8)    // 256 octs per row

__global__ void zero_out_kernel(float* out) {
    out[0] = 0.0f;
}

struct F8 { float f[8]; };

// 32-byte load with L2 evict_last (the only load width ptxas accepts the
// modifier on for sm_103): pin phi in L2 across graph replays.
__device__ __forceinline__ F8 ldg_el8(const float* p) {
    unsigned long long a, b, c, d;
    asm volatile("ld.global.nc.L2::evict_last.v4.b64 {%0,%1,%2,%3}, [%4];"
                 : "=l"(a), "=l"(b), "=l"(c), "=l"(d) : "l"(p));
    F8 r;
    r.f[0] = __uint_as_float((unsigned)a); r.f[1] = __uint_as_float((unsigned)(a >> 32));
    r.f[2] = __uint_as_float((unsigned)b); r.f[3] = __uint_as_float((unsigned)(b >> 32));
    r.f[4] = __uint_as_float((unsigned)c); r.f[5] = __uint_as_float((unsigned)(c >> 32));
    r.f[6] = __uint_as_float((unsigned)d); r.f[7] = __uint_as_float((unsigned)(d >> 32));
    return r;
}

__global__ __launch_bounds__(TPB)
void flow_energy_kernel(const float* __restrict__ phi, float* __restrict__ out) {
    const int oct = blockIdx.x * TPB + threadIdx.x;    // 0..255 (8-col group)
    const int j0  = oct * 8;                            // first column of this oct
    const int r0  = blockIdx.y * ROWS_PER_THREAD;       // first row of this tile

    // Front-batched 32B loads: rows r0-1 .. r0+ROWS (row-clamped; clamped rows
    // are only consumed by one-sided branches where they drop out).
    F8 v[ROWS_PER_THREAD + 2];
    #pragma unroll
    for (int i = 0; i < ROWS_PER_THREAD + 2; i++) {
        int r = r0 - 1 + i;
        r = (r < 0) ? 0 : ((r > NXg - 1) ? NXg - 1 : r);
        v[i] = ldg_el8(phi + (size_t)r * NYg + j0);
    }

    const int  lane       = threadIdx.x & 31;
    const bool left_edge  = (j0 == 0);
    const bool right_edge = (j0 + 8 == NYg);

    float acc = 0.0f;

    #pragma unroll
    for (int rr = 0; rr < ROWS_PER_THREAD; rr++) {
        const int r = r0 + rr;
        const F8& prev = v[rr];
        const F8& cur  = v[rr + 1];
        const F8& next = v[rr + 2];

        // ---- vx (row-direction gradient); sign irrelevant (squared) ----
        if (r == 0) {
            #pragma unroll
            for (int k = 0; k < 8; k++) {
                float vx = (next.f[k] - cur.f[k]) * INV_H;
                acc += vx * vx;
            }
        } else if (r == NXg - 1) {
            #pragma unroll
            for (int k = 0; k < 8; k++) {
                float vx = (cur.f[k] - prev.f[k]) * INV_H;
                acc += vx * vx;
            }
        } else {
            #pragma unroll
            for (int k = 0; k < 8; k++) {
                float vx = (next.f[k] - prev.f[k]) * INV_2H;
                acc += vx * vx;
            }
        }

        // ---- vy (column-direction gradient) ----
        // Neighbors from adjacent lanes' registers; warp-edge lanes use a
        // predicated scalar load (rare, 1 wavefront).
        float l  = __shfl_up_sync(0xFFFFFFFFu, cur.f[7], 1);
        float rt = __shfl_down_sync(0xFFFFFFFFu, cur.f[0], 1);
        if (lane == 0 && !left_edge)
            l = __ldg(&phi[(size_t)r * NYg + j0 - 1]);
        if (lane == 31 && !right_edge)
            rt = __ldg(&phi[(size_t)r * NYg + j0 + 8]);

        float vy0 = left_edge  ? (cur.f[1] - cur.f[0]) * INV_H
                               : (cur.f[1] - l) * INV_2H;
        acc += vy0 * vy0;
        #pragma unroll
        for (int k = 1; k < 7; k++) {
            float vy = (cur.f[k + 1] - cur.f[k - 1]) * INV_2H;
            acc += vy * vy;
        }
        float vy7 = right_edge ? (cur.f[7] - cur.f[6]) * INV_H
                               : (rt - cur.f[6]) * INV_2H;
        acc += vy7 * vy7;
    }

    // ---- warp reduce ----
    #pragma unroll
    for (int o = 16; o > 0; o >>= 1)
        acc += __shfl_xor_sync(0xFFFFFFFFu, acc, o);

    // ---- block reduce ----
    __shared__ float warp_sums[TPB / 32];
    const int wid = threadIdx.x >> 5;
    if (lane == 0) warp_sums[wid] = acc;
    __syncthreads();

    if (wid == 0) {
        float s = (lane < TPB / 32) ? warp_sums[lane] : 0.0f;
        #pragma unroll
        for (int o = 2; o > 0; o >>= 1)
            s += __shfl_xor_sync(0xFFFFFFFFu, s, o);
        if (lane == 0)
            atomicAdd(out, 0.5f * s);
    }
}

extern "C" void kernel_launch(void* const* d_in, const int* in_sizes, int n_in,
                              void* d_out, int out_size) {
    // d_in[0] = pos (unused), d_in[1] = potential_field [2048*2048] fp32
    const float* phi = (const float*)d_in[1];
    float* out = (float*)d_out;

    zero_out_kernel<<<1, 1>>>(out);

    dim3 grid(OPR / TPB, NXg / ROWS_PER_THREAD);  // (2, 512) = 1024 blocks
    flow_energy_kernel<<<grid, TPB>>>(phi, out);
}

// round 13
// speedup vs baseline: 1.0573x; 1.0573x over previous
#include <cuda_runtime.h>
#include <cuda_bf16.h>
#include <cstdint>

// Problem constants (match reference)
#define NXg 2048
#define NYg 2048
#define INV_H  2048.0f   // 1/hx = 1/hy
#define INV_2H 1024.0f   // 1/(2hx)

#define ROWS_PER_THREAD 4
#define TPB 256
#define GRID_X (NYg / 4 / TPB)            // 2
#define GRID_Y (NXg / ROWS_PER_THREAD)    // 512
#define NBLOCKS (GRID_X * GRID_Y)         // 1024

// Cross-block accumulator, self-resetting (single-kernel graph, no pre-zero).
__device__ float    g_scratch = 0.0f;
__device__ unsigned g_count   = 0u;

__global__ __launch_bounds__(TPB)
void flow_energy_kernel(const float* __restrict__ phi, float* __restrict__ out) {
    const int quad = blockIdx.x * TPB + threadIdx.x;   // column quad index (0..511)
    const int j0   = quad * 4;                          // first column of this quad
    const int r0   = blockIdx.y * ROWS_PER_THREAD;      // first row of this tile
    const int qstride = NYg / 4;

    const float4* __restrict__ phi4 = reinterpret_cast<const float4*>(phi);

    // Front-batched loads: rows r0-1 .. r0+ROWS (row-clamped; clamped rows are
    // only consumed by one-sided branches where they drop out).
    float4 v[ROWS_PER_THREAD + 2];
    #pragma unroll
    for (int i = 0; i < ROWS_PER_THREAD + 2; i++) {
        int r = r0 - 1 + i;
        r = (r < 0) ? 0 : ((r > NXg - 1) ? NXg - 1 : r);
        v[i] = phi4[r * qstride + quad];
    }

    const int  lane       = threadIdx.x & 31;
    const bool left_edge  = (j0 == 0);
    const bool right_edge = (j0 + 4 == NYg);

    float acc = 0.0f;

    #pragma unroll
    for (int rr = 0; rr < ROWS_PER_THREAD; rr++) {
        const int r = r0 + rr;
        const float4 prev = v[rr];
        const float4 cur  = v[rr + 1];
        const float4 next = v[rr + 2];

        // ---- vx (row-direction gradient); sign irrelevant (squared) ----
        float vx0, vx1, vx2, vx3;
        if (r == 0) {
            vx0 = (next.x - cur.x) * INV_H;
            vx1 = (next.y - cur.y) * INV_H;
            vx2 = (next.z - cur.z) * INV_H;
            vx3 = (next.w - cur.w) * INV_H;
        } else if (r == NXg - 1) {
            vx0 = (cur.x - prev.x) * INV_H;
            vx1 = (cur.y - prev.y) * INV_H;
            vx2 = (cur.z - prev.z) * INV_H;
            vx3 = (cur.w - prev.w) * INV_H;
        } else {
            vx0 = (next.x - prev.x) * INV_2H;
            vx1 = (next.y - prev.y) * INV_2H;
            vx2 = (next.z - prev.z) * INV_2H;
            vx3 = (next.w - prev.w) * INV_2H;
        }

        // ---- vy (column-direction gradient) ----
        float l  = __shfl_up_sync(0xFFFFFFFFu, cur.w, 1);
        float rt = __shfl_down_sync(0xFFFFFFFFu, cur.x, 1);
        if (lane == 0 && !left_edge)
            l = __ldg(&phi[r * NYg + j0 - 1]);
        if (lane == 31 && !right_edge)
            rt = __ldg(&phi[r * NYg + j0 + 4]);

        float vy0 = left_edge  ? (cur.y - cur.x) * INV_H : (cur.y - l) * INV_2H;
        float vy1 = (cur.z - cur.x) * INV_2H;
        float vy2 = (cur.w - cur.y) * INV_2H;
        float vy3 = right_edge ? (cur.w - cur.z) * INV_H : (rt - cur.z) * INV_2H;

        acc += vx0 * vx0 + vx1 * vx1 + vx2 * vx2 + vx3 * vx3;
        acc += vy0 * vy0 + vy1 * vy1 + vy2 * vy2 + vy3 * vy3;
    }

    // ---- warp reduce ----
    #pragma unroll
    for (int o = 16; o > 0; o >>= 1)
        acc += __shfl_xor_sync(0xFFFFFFFFu, acc, o);

    // ---- block reduce ----
    __shared__ float warp_sums[TPB / 32];
    const int wid = threadIdx.x >> 5;
    if (lane == 0) warp_sums[wid] = acc;
    __syncthreads();

    if (threadIdx.x == 0) {
        float s = warp_sums[0];
        #pragma unroll
        for (int w = 1; w < TPB / 32; w++) s += warp_sums[w];
        s *= 0.5f;

        // Relaxed add of this block's partial into the scratch accumulator.
        atomicAdd(&g_scratch, s);

        // acq_rel RMW on the completion counter:
        //   release: orders this block's scratch-add before its count-inc.
        //   acquire: the last block observes all prior releases -> all adds.
        // (No gpu-scope fence / L1 flush — that was R5's 1.8us mistake.)
        unsigned ticket;
        asm volatile("atom.acq_rel.gpu.global.add.u32 %0, [%1], 1;"
                     : "=r"(ticket) : "l"(&g_count) : "memory");
        if (ticket == NBLOCKS - 1) {
            out[0]    = *((volatile float*)&g_scratch);
            g_scratch = 0.0f;    // reset for the next graph replay; ordered by
            g_count   = 0u;      // the kernel boundary before the next launch
        }
    }
}

extern "C" void kernel_launch(void* const* d_in, const int* in_sizes, int n_in,
                              void* d_out, int out_size) {
    // d_in[0] = pos (unused), d_in[1] = potential_field [2048*2048] fp32
    const float* phi = (const float*)d_in[1];
    float* out = (float*)d_out;

    dim3 grid(GRID_X, GRID_Y);   // (2, 512) = 1024 blocks, single graph node
    flow_energy_kernel<<<grid, TPB>>>(phi, out);
}